// round 16
// baseline (speedup 1.0000x reference)
#include <cuda_runtime.h>
#include <cuda_bf16.h>
#include <math.h>

// ---------------------------------------------------------------------------
// SparseConvNet: 6 partial-conv layers. N=4, H=W=1024.
// Round 16: revert K=7 to R14 single-pass B cache (two-pass regressed);
// keep only L1's float4-window staging from R15. Everything else = R14.
// ---------------------------------------------------------------------------

#define HW   (1024 * 1024)
#define IMW  1024
#define NPIX (4LL * HW)

__device__ float  g_h0[4 * 16 * HW];
__device__ float  g_h1[4 * 16 * HW];
__device__ float  g_m0[4 * HW];
__device__ float  g_m1[4 * HW];
__device__ double g_stats[6 * 32];
__device__ unsigned int g_bfrag[103 * 2 * 32 * 4];  // 49+25+9+9 + 11 (L1) taps

typedef unsigned long long u64;
typedef unsigned int u32;
typedef unsigned short u16;

__device__ __forceinline__ u32 smem_u32(const void* p) {
    u32 a;
    asm("{ .reg .u64 t; cvta.to.shared.u64 t, %1; cvt.u32.u64 %0, t; }"
        : "=r"(a) : "l"(p));
    return a;
}
__device__ __forceinline__ void ldsm4(u32* r, u32 a) {
    asm volatile("ldmatrix.sync.aligned.m8n8.x4.shared.b16 {%0,%1,%2,%3}, [%4];"
                 : "=r"(r[0]), "=r"(r[1]), "=r"(r[2]), "=r"(r[3]) : "r"(a));
}
__device__ __forceinline__ void mma16816(float* d, const u32* a, u32 b0, u32 b1) {
    asm volatile(
        "mma.sync.aligned.m16n8k16.row.col.f32.bf16.bf16.f32 "
        "{%0,%1,%2,%3}, {%4,%5,%6,%7}, {%8,%9}, {%0,%1,%2,%3};"
        : "+f"(d[0]), "+f"(d[1]), "+f"(d[2]), "+f"(d[3])
        : "r"(a[0]), "r"(a[1]), "r"(a[2]), "r"(a[3]), "r"(b0), "r"(b1));
}
// truncation hi/lo split (scalar, used in prep): hi = top16, lo = RN(t - hi)
__device__ __forceinline__ void bsplit(float t, u16& h, u16& l) {
    u32 u = __float_as_uint(t);
    h = (u16)(u >> 16);
    float fh = __uint_as_float(u & 0xFFFF0000u);
    l = __bfloat16_as_ushort(__float2bfloat16(t - fh));
}
// packed pair split: h = hi16(v0)|hi16(v1)<<16 via PRMT; l = bf16x2 of residuals
__device__ __forceinline__ void bsplit2(float v0, float v1, u32& h, u32& l) {
    u32 u0 = __float_as_uint(v0), u1 = __float_as_uint(v1);
    asm("prmt.b32 %0, %1, %2, 0x7632;" : "=r"(h) : "r"(u0), "r"(u1));
    float f0 = __uint_as_float(u0 & 0xFFFF0000u);
    float f1 = __uint_as_float(u1 & 0xFFFF0000u);
    asm("cvt.rn.bf16x2.f32 %0, %1, %2;" : "=r"(l) : "f"(v1 - f1), "f"(v0 - f0));
}

// ---------------------------------------------------------------------------
// Combined prep: zero stats + B fragments.
// Taps 0..48: L2(K=7); 49..73: L3(K=5); 74..82: L4(K=3); 83..91: L5(K=3);
// 92..102: L1 (11 dy-taps, "ci" = dx of the 11-wide row, zero-padded to 16).
// ---------------------------------------------------------------------------
__global__ void prep_all_b(const float* __restrict__ w1, const float* __restrict__ w2,
                           const float* __restrict__ w3, const float* __restrict__ w4,
                           const float* __restrict__ w5,
                           u32* __restrict__ bf, double* __restrict__ st) {
    if (blockIdx.x == 0 && threadIdx.x < 192) st[threadIdx.x] = 0.0;
    const int total = 103 * 2 * 32;
    for (int i = blockIdx.x * blockDim.x + threadIdx.x; i < total;
         i += gridDim.x * blockDim.x) {
        int lane = i & 31;
        int half = (i >> 5) & 1;
        int gt = i >> 6;
        int k0 = (lane & 3) * 2, nn = lane >> 2;
        u32 out[4];
        if (gt >= 92) {
            int dy = gt - 92;
#pragma unroll
            for (int t = 0; t < 2; t++) {
#pragma unroll
                for (int kk = 0; kk < 2; kk++) {
                    int co = t * 8 + nn;
                    int dx = k0 + kk * 8;
                    float v0 = (dx < 11) ? w1[co * 121 + dy * 11 + dx] : 0.f;
                    float v1 = (dx + 1 < 11) ? w1[co * 121 + dy * 11 + dx + 1] : 0.f;
                    u16 h0, l0, h1, l1;
                    bsplit(v0, h0, l0);
                    bsplit(v1, h1, l1);
                    u16 a = half ? l0 : h0, b = half ? l1 : h1;
                    out[t * 2 + kk] = (u32)a | ((u32)b << 16);
                }
            }
        } else {
            const float* w;
            int K, tap;
            if (gt < 49)      { w = w2; K = 7; tap = gt; }
            else if (gt < 74) { w = w3; K = 5; tap = gt - 49; }
            else if (gt < 83) { w = w4; K = 3; tap = gt - 74; }
            else              { w = w5; K = 3; tap = gt - 83; }
            int dy = tap / K, dx = tap - dy * K;
#pragma unroll
            for (int t = 0; t < 2; t++) {
#pragma unroll
                for (int kk = 0; kk < 2; kk++) {
                    int co = t * 8 + nn;
                    int k = k0 + kk * 8;
                    float v0 = w[((co * 16 + k) * K + dy) * K + dx];
                    float v1 = w[((co * 16 + k + 1) * K + dy) * K + dx];
                    u16 h0, l0, h1, l1;
                    bsplit(v0, h0, l0);
                    bsplit(v1, h1, l1);
                    u16 a = half ? l0 : h0, b = half ? l1 : h1;
                    out[t * 2 + kk] = (u32)a | ((u32)b << 16);
                }
            }
        }
        ((uint4*)bf)[i] = make_uint4(out[0], out[1], out[2], out[3]);
    }
}

// ---------------------------------------------------------------------------
// Tensor-core partial-conv layer (cin=cout=16), layers 2-5. TY=8, fused
// mask+A staging, single-pass B register cache (R14-proven).
// ---------------------------------------------------------------------------
template <int K, bool AFF>
__global__ void __launch_bounds__(128, (K <= 3) ? 4 : 3) tmma_conv_k(
    const float* __restrict__ in, long long inNS,
    const float* __restrict__ mk, long long mkNS,
    const u32* __restrict__ bfrag, const float* __restrict__ bias,
    const double* __restrict__ stPrev,
    const float* __restrict__ gamPrev, const float* __restrict__ betPrev,
    float* __restrict__ outH, float* __restrict__ outM,
    double* __restrict__ stats) {
    constexpr int TY = 8, P = K / 2, TILE = 64;
    constexpr int NPX = TILE + K - 1;
    constexpr int NPXW = (NPX + 7) & ~7;
    constexpr int R = K + TY - 1;
    constexpr int ROWB = NPXW * 32;
    constexpr int SR_OFF = 0;
    constexpr int AB_OFF = 1024;
    constexpr int MK_OFF = AB_OFF + 128;
    constexpr int AH_OFF = ((MK_OFF + R * NPXW * 4 + 127) / 128) * 128;
    constexpr int AL_OFF = AH_OFF + R * ROWB;

    extern __shared__ char smx[];
    float*  sR  = (float*)(smx + SR_OFF);
    float2* sAB = (float2*)(smx + AB_OFF);
    float*  sMk = (float*)(smx + MK_OFF);
    const u32 sb = smem_u32(smx);

    const int tid = threadIdx.x;
    const int wid = tid >> 5;
    const int lane = tid & 31;
    const int n  = blockIdx.z;
    const int x0 = blockIdx.x * TILE;
    const int y0 = blockIdx.y * TY;

    if (tid < 16) {
        if (AFF) {
            double mean = stPrev[tid] / (double)NPIX;
            double var  = stPrev[16 + tid] / (double)NPIX - mean * mean;
            float inv = rsqrtf((float)var + 1e-5f);
            float a = gamPrev[tid] * inv;
            sAB[tid] = make_float2(a, betPrev[tid] - (float)mean * a);
        } else {
            sAB[tid] = make_float2(1.f, 0.f);
        }
    }
    __syncthreads();

    float2 abr[16];
#pragma unroll
    for (int ci = 0; ci < 16; ci++) abr[ci] = sAB[ci];

    // ---- fused mask + A staging (single loop) ----
    const float* mkn = mk + (long long)n * mkNS;
    const float* inn = in + (long long)n * inNS;
    for (int i = tid; i < R * NPX; i += 128) {
        int r = i / NPX, p = i - r * NPX;
        int gy = y0 - P + r, gx = x0 - P + p;
        bool ok = (unsigned)gy < 1024u && (unsigned)gx < 1024u;
        long long goff = (long long)gy * IMW + gx;
        float m = ok ? mkn[goff] : 0.f;
        sMk[r * NPXW + p] = m;
        const float* ip = inn + goff;
        u32 hp[8], lp[8];
#pragma unroll
        for (int c2 = 0; c2 < 8; c2++) {
            float v0 = ok ? ip[(long long)(2 * c2) * HW] : 0.f;
            float v1 = ok ? ip[(long long)(2 * c2 + 1) * HW] : 0.f;
            if (AFF) {
                v0 = fmaxf(fmaf(v0, abr[2 * c2].x, abr[2 * c2].y), 0.f);
                v1 = fmaxf(fmaf(v1, abr[2 * c2 + 1].x, abr[2 * c2 + 1].y), 0.f);
            }
            v0 *= m;
            v1 *= m;
            bsplit2(v0, v1, hp[c2], lp[c2]);
        }
        u32 s = ((p >> 2) & 1) * 16;
        char* ah = smx + AH_OFF + r * ROWB + p * 32;
        char* al = smx + AL_OFF + r * ROWB + p * 32;
        *(uint4*)(ah + s)        = make_uint4(hp[0], hp[1], hp[2], hp[3]);
        *(uint4*)(ah + (16 ^ s)) = make_uint4(hp[4], hp[5], hp[6], hp[7]);
        *(uint4*)(al + s)        = make_uint4(lp[0], lp[1], lp[2], lp[3]);
        *(uint4*)(al + (16 ^ s)) = make_uint4(lp[4], lp[5], lp[6], lp[7]);
    }
    __syncthreads();

    const int seg = wid;
    float D[TY][2][4];
#pragma unroll
    for (int y = 0; y < TY; y++)
#pragma unroll
        for (int t = 0; t < 2; t++)
#pragma unroll
            for (int j = 0; j < 4; j++) D[y][t][j] = 0.f;

    const int l15 = lane & 15;
    const int kh = lane >> 4;
    const uint4* bf4 = (const uint4*)bfrag;

#pragma unroll 1
    for (int dx = 0; dx < K; dx++) {
        u32 sw = (u32)(((l15 + dx) >> 2) & 1);
        u32 apx = (u32)(seg * 16 + l15 + dx);
        u32 aoff = apx * 32 + (((u32)kh ^ sw) * 16);
        u32 aH = sb + AH_OFF + aoff;
        u32 aL = sb + AL_OFF + aoff;
        uint4 BH[K], BL[K];
#pragma unroll
        for (int dy = 0; dy < K; dy++) {
            BH[dy] = bf4[((dy * K + dx) * 2 + 0) * 32 + lane];
            BL[dy] = bf4[((dy * K + dx) * 2 + 1) * 32 + lane];
        }
#pragma unroll
        for (int r = 0; r < R; r++) {
            u32 Ah[4], Al[4];
            ldsm4(Ah, aH + r * ROWB);
            ldsm4(Al, aL + r * ROWB);
#pragma unroll
            for (int dy = 0; dy < K; dy++) {
                const int y = r - dy;
                if (y >= 0 && y < TY) {
                    mma16816(D[y][0], Ah, BH[dy].x, BH[dy].y);
                    mma16816(D[y][1], Ah, BH[dy].z, BH[dy].w);
                    mma16816(D[y][0], Al, BH[dy].x, BH[dy].y);
                    mma16816(D[y][1], Al, BH[dy].z, BH[dy].w);
                    mma16816(D[y][0], Ah, BL[dy].x, BL[dy].y);
                    mma16816(D[y][1], Ah, BL[dy].z, BL[dy].w);
                }
            }
        }
    }

    const int pxl = lane & 15, half = lane >> 4;
    float hsum[R], hmax[R];
    {
        const float* mb = sMk + seg * 16 + pxl;
#pragma unroll
        for (int r = 0; r < R; r++) {
            float s = 0.f, mx = 0.f;
#pragma unroll
            for (int dxm = 0; dxm < K; dxm++) {
                float m = mb[r * NPXW + dxm];
                s += m;
                mx = fmaxf(mx, m);
            }
            hsum[r] = s;
            hmax[r] = mx;
        }
    }
    float invv[4];
#pragma unroll
    for (int j = 0; j < 4; j++) {
        int y = half + 2 * j;
        float s = 0.f, mx = 0.f;
#pragma unroll
        for (int dy = 0; dy < K; dy++) {
            s += hsum[y + dy];
            mx = fmaxf(mx, hmax[y + dy]);
        }
        invv[j] = 1.0f / (s + 1e-8f);
        outM[(long long)n * HW + (long long)(y0 + y) * IMW + x0 + seg * 16 + pxl] = mx;
    }

    float bco[4];
#pragma unroll
    for (int t = 0; t < 2; t++)
#pragma unroll
        for (int j = 0; j < 2; j++)
            bco[t * 2 + j] = bias[t * 8 + (lane & 3) * 2 + j];
    float p1[4] = {0.f, 0.f, 0.f, 0.f}, p2[4] = {0.f, 0.f, 0.f, 0.f};
    const int pxa = seg * 16 + (lane >> 2);

#pragma unroll
    for (int y = 0; y < TY; y++) {
        float vsel = invv[y >> 1];
        float inva = __shfl_sync(0xffffffffu, vsel, ((y & 1) << 4) + (lane >> 2));
        float invb = __shfl_sync(0xffffffffu, vsel, ((y & 1) << 4) + (lane >> 2) + 8);
        int gy = y0 + y;
        float* hb = outH + (long long)n * 16 * HW + (long long)gy * IMW + x0;
#pragma unroll
        for (int t = 0; t < 2; t++) {
#pragma unroll
            for (int j = 0; j < 2; j++) {
                int co = t * 8 + (lane & 3) * 2 + j;
                float bc = bco[t * 2 + j];
                float v0 = fmaf(D[y][t][j], inva, bc);
                float v1 = fmaf(D[y][t][j + 2], invb, bc);
                hb[(long long)co * HW + pxa] = v0;
                hb[(long long)co * HW + pxa + 8] = v1;
                p1[t * 2 + j] += v0 + v1;
                p2[t * 2 + j] = fmaf(v0, v0, fmaf(v1, v1, p2[t * 2 + j]));
            }
        }
    }
#pragma unroll
    for (int k = 0; k < 4; k++) {
#pragma unroll
        for (int o = 4; o < 32; o <<= 1) {
            p1[k] += __shfl_xor_sync(0xffffffffu, p1[k], o);
            p2[k] += __shfl_xor_sync(0xffffffffu, p2[k], o);
        }
    }
    if (lane < 4) {
#pragma unroll
        for (int t = 0; t < 2; t++)
#pragma unroll
            for (int j = 0; j < 2; j++) {
                int co = t * 8 + lane * 2 + j;
                sR[(co * 2 + 0) * 4 + wid] = p1[t * 2 + j];
                sR[(co * 2 + 1) * 4 + wid] = p2[t * 2 + j];
            }
    }
    __syncthreads();
    if (tid < 32) {
        int co = tid >> 1, which = tid & 1;
        float v = sR[tid * 4 + 0] + sR[tid * 4 + 1] + sR[tid * 4 + 2] + sR[tid * 4 + 3];
        atomicAdd(&stats[which * 16 + co], (double)v);
    }
}

// ---------------------------------------------------------------------------
// Layer 1 tensor-core partial conv (cin=1, K=11), TY=8: dx taps packed as MMA
// channels. Vectorized A staging: 4 px/thread via float4 register window.
// ---------------------------------------------------------------------------
__global__ void __launch_bounds__(128, 2) tmma_conv1_k(
    const float* __restrict__ in, long long inNS,
    const float* __restrict__ mk, long long mkNS,
    const u32* __restrict__ bfrag, const float* __restrict__ bias,
    float* __restrict__ outH, float* __restrict__ outM,
    double* __restrict__ stats) {
    constexpr int K = 11, TY = 8, P = 5, TILE = 64;
    constexpr int R = K + TY - 1;          // 18 window rows
    constexpr int MW = 80;                 // mask/xm row width (64+15 pad)
    constexpr int MUSE = TILE + K - 1;     // 74 meaningful columns
    constexpr int ROWB = TILE * 32;        // A row bytes (64 px * 32B)
    constexpr int SR_OFF = 0;
    constexpr int MK_OFF = 1024;
    constexpr int XM_OFF = MK_OFF + R * MW * 4;
    constexpr int AH_OFF = ((XM_OFF + R * MW * 4 + 127) / 128) * 128;
    constexpr int AL_OFF = AH_OFF + R * ROWB;

    extern __shared__ char smx[];
    float* sR  = (float*)(smx + SR_OFF);
    float* sMk = (float*)(smx + MK_OFF);
    float* sXm = (float*)(smx + XM_OFF);
    const u32 sb = smem_u32(smx);

    const int tid = threadIdx.x;
    const int wid = tid >> 5;
    const int lane = tid & 31;
    const int n  = blockIdx.z;
    const int x0 = blockIdx.x * TILE;
    const int y0 = blockIdx.y * TY;

    // ---- stage mask + xm rows ----
    const float* mkn = mk + (long long)n * mkNS;
    const float* inn = in + (long long)n * inNS;
    for (int i = tid; i < R * MW; i += 128) {
        int r = i / MW, j = i - r * MW;
        int gy = y0 - P + r, gx = x0 - P + j;
        float m = 0.f, v = 0.f;
        if ((unsigned)gy < 1024u && (unsigned)gx < 1024u && j < MUSE) {
            m = mkn[gy * IMW + gx];
            v = inn[gy * IMW + gx];
        }
        sMk[i] = m;
        sXm[i] = v * m;
    }
    __syncthreads();

    // ---- stage A: 4 px/thread, float4 register window (20 floats) ----
    for (int i = tid; i < R * 16; i += 128) {
        int r = i >> 4, q = i & 15;
        int p = q * 4;
        const float4* xr4 = (const float4*)(sXm + r * MW + p);
        float w[20];
        *(float4*)(w + 0)  = xr4[0];
        *(float4*)(w + 4)  = xr4[1];
        *(float4*)(w + 8)  = xr4[2];
        *(float4*)(w + 12) = xr4[3];
        *(float4*)(w + 16) = xr4[4];
#pragma unroll
        for (int j = 0; j < 4; j++) {
            int pj = p + j;
            u32 hp[8], lp[8];
#pragma unroll
            for (int c2 = 0; c2 < 8; c2++)
                bsplit2(w[j + 2 * c2], w[j + 2 * c2 + 1], hp[c2], lp[c2]);
            u32 s = ((pj >> 2) & 1) * 16;
            char* ah = smx + AH_OFF + r * ROWB + pj * 32;
            char* al = smx + AL_OFF + r * ROWB + pj * 32;
            *(uint4*)(ah + s)        = make_uint4(hp[0], hp[1], hp[2], hp[3]);
            *(uint4*)(ah + (16 ^ s)) = make_uint4(hp[4], hp[5], hp[6], hp[7]);
            *(uint4*)(al + s)        = make_uint4(lp[0], lp[1], lp[2], lp[3]);
            *(uint4*)(al + (16 ^ s)) = make_uint4(lp[4], lp[5], lp[6], lp[7]);
        }
    }
    __syncthreads();

    // ---- MMA mainloop: r-sweep, B per dy from global (L1-resident) ----
    const int seg = wid;
    float D[TY][2][4];
#pragma unroll
    for (int y = 0; y < TY; y++)
#pragma unroll
        for (int t = 0; t < 2; t++)
#pragma unroll
            for (int j = 0; j < 4; j++) D[y][t][j] = 0.f;

    const int l15 = lane & 15;
    const int kh = lane >> 4;
    const uint4* bf4 = (const uint4*)bfrag;
    {
        u32 sw = (u32)((l15 >> 2) & 1);
        u32 aoff = (u32)(seg * 16 + l15) * 32 + (((u32)kh ^ sw) * 16);
        u32 aH = sb + AH_OFF + aoff;
        u32 aL = sb + AL_OFF + aoff;
#pragma unroll
        for (int r = 0; r < R; r++) {
            u32 Ah[4], Al[4];
            ldsm4(Ah, aH + r * ROWB);
            ldsm4(Al, aL + r * ROWB);
#pragma unroll
            for (int dy = 0; dy < K; dy++) {
                const int y = r - dy;
                if (y >= 0 && y < TY) {
                    uint4 BH = bf4[(dy * 2 + 0) * 32 + lane];
                    uint4 BL = bf4[(dy * 2 + 1) * 32 + lane];
                    mma16816(D[y][0], Ah, BH.x, BH.y);
                    mma16816(D[y][1], Ah, BH.z, BH.w);
                    mma16816(D[y][0], Al, BH.x, BH.y);
                    mma16816(D[y][1], Al, BH.z, BH.w);
                    mma16816(D[y][0], Ah, BL.x, BL.y);
                    mma16816(D[y][1], Ah, BL.z, BL.w);
                }
            }
        }
    }

    // ---- separable mask-sum conv + maxpool (lane owns rows half+2j) ----
    const int pxl = lane & 15, half = lane >> 4;
    float hsum[R], hmax[R];
    {
        const float* mb = sMk + seg * 16 + pxl;
#pragma unroll
        for (int r = 0; r < R; r++) {
            float s = 0.f, mx = 0.f;
#pragma unroll
            for (int dxm = 0; dxm < K; dxm++) {
                float m = mb[r * MW + dxm];
                s += m;
                mx = fmaxf(mx, m);
            }
            hsum[r] = s;
            hmax[r] = mx;
        }
    }
    float invv[4];
#pragma unroll
    for (int j = 0; j < 4; j++) {
        int y = half + 2 * j;
        float s = 0.f, mx = 0.f;
#pragma unroll
        for (int dy = 0; dy < K; dy++) {
            s += hsum[y + dy];
            mx = fmaxf(mx, hmax[y + dy]);
        }
        invv[j] = 1.0f / (s + 1e-8f);
        outM[(long long)n * HW + (long long)(y0 + y) * IMW + x0 + seg * 16 + pxl] = mx;
    }

    // ---- epilogue ----
    float bco[4];
#pragma unroll
    for (int t = 0; t < 2; t++)
#pragma unroll
        for (int j = 0; j < 2; j++)
            bco[t * 2 + j] = bias[t * 8 + (lane & 3) * 2 + j];
    float p1[4] = {0.f, 0.f, 0.f, 0.f}, p2[4] = {0.f, 0.f, 0.f, 0.f};
    const int pxa = seg * 16 + (lane >> 2);

#pragma unroll
    for (int y = 0; y < TY; y++) {
        float vsel = invv[y >> 1];
        float inva = __shfl_sync(0xffffffffu, vsel, ((y & 1) << 4) + (lane >> 2));
        float invb = __shfl_sync(0xffffffffu, vsel, ((y & 1) << 4) + (lane >> 2) + 8);
        int gy = y0 + y;
        float* hb = outH + (long long)n * 16 * HW + (long long)gy * IMW + x0;
#pragma unroll
        for (int t = 0; t < 2; t++) {
#pragma unroll
            for (int j = 0; j < 2; j++) {
                int co = t * 8 + (lane & 3) * 2 + j;
                float bc = bco[t * 2 + j];
                float v0 = fmaf(D[y][t][j], inva, bc);
                float v1 = fmaf(D[y][t][j + 2], invb, bc);
                hb[(long long)co * HW + pxa] = v0;
                hb[(long long)co * HW + pxa + 8] = v1;
                p1[t * 2 + j] += v0 + v1;
                p2[t * 2 + j] = fmaf(v0, v0, fmaf(v1, v1, p2[t * 2 + j]));
            }
        }
    }
#pragma unroll
    for (int k = 0; k < 4; k++) {
#pragma unroll
        for (int o = 4; o < 32; o <<= 1) {
            p1[k] += __shfl_xor_sync(0xffffffffu, p1[k], o);
            p2[k] += __shfl_xor_sync(0xffffffffu, p2[k], o);
        }
    }
    if (lane < 4) {
#pragma unroll
        for (int t = 0; t < 2; t++)
#pragma unroll
            for (int j = 0; j < 2; j++) {
                int co = t * 8 + lane * 2 + j;
                sR[(co * 2 + 0) * 4 + wid] = p1[t * 2 + j];
                sR[(co * 2 + 1) * 4 + wid] = p2[t * 2 + j];
            }
    }
    __syncthreads();
    if (tid < 32) {
        int co = tid >> 1, which = tid & 1;
        float v = sR[tid * 4 + 0] + sR[tid * 4 + 1] + sR[tid * 4 + 2] + sR[tid * 4 + 3];
        atomicAdd(&stats[which * 16 + co], (double)v);
    }
}

// ---------------------------------------------------------------------------
// Layer 6: 1x1 partial conv, 16 -> 1; float4 (4 px/thread); affine in-block.
// ---------------------------------------------------------------------------
__global__ void conv1x1_k(const float* __restrict__ h,
                          const float* __restrict__ mk,
                          const float* __restrict__ w6,
                          const float* __restrict__ b6,
                          const double* __restrict__ st5,
                          const float* __restrict__ g5,
                          const float* __restrict__ bt5,
                          float* __restrict__ y,
                          double* __restrict__ stats) {
    __shared__ float swv[16];
    __shared__ float2 sab[16];
    __shared__ float r1[8], r2[8];
    if (threadIdx.x < 16) {
        swv[threadIdx.x] = w6[threadIdx.x];
        double mean = st5[threadIdx.x] / (double)NPIX;
        double var  = st5[16 + threadIdx.x] / (double)NPIX - mean * mean;
        float inv = rsqrtf((float)var + 1e-5f);
        float a = g5[threadIdx.x] * inv;
        sab[threadIdx.x] = make_float2(a, bt5[threadIdx.x] - (float)mean * a);
    }
    __syncthreads();
    float bb = b6[0];
    float p1 = 0.f, p2 = 0.f;
    const float4* mk4 = (const float4*)mk;
    float4* y4 = (float4*)y;
    for (long long i = (long long)blockIdx.x * blockDim.x + threadIdx.x;
         i < 1LL * HW; i += (long long)gridDim.x * blockDim.x) {
        long long n = i >> 18;
        long long p4 = i & ((HW >> 2) - 1);
        float4 m = mk4[i];
        float4 acc = make_float4(0.f, 0.f, 0.f, 0.f);
        const float4* hb = (const float4*)(h + (n * 16) * HW) + p4;
#pragma unroll
        for (int c = 0; c < 16; c++) {
            float4 v = hb[(long long)c * (HW >> 2)];
            float2 ab = sab[c];
            float wv = swv[c];
            acc.x = fmaf(wv, fmaxf(fmaf(v.x, ab.x, ab.y), 0.f), acc.x);
            acc.y = fmaf(wv, fmaxf(fmaf(v.y, ab.x, ab.y), 0.f), acc.y);
            acc.z = fmaf(wv, fmaxf(fmaf(v.z, ab.x, ab.y), 0.f), acc.z);
            acc.w = fmaf(wv, fmaxf(fmaf(v.w, ab.x, ab.y), 0.f), acc.w);
        }
        float4 o;
        o.x = fmaf(acc.x * m.x, 1.0f / (m.x + 1e-8f), bb);
        o.y = fmaf(acc.y * m.y, 1.0f / (m.y + 1e-8f), bb);
        o.z = fmaf(acc.z * m.z, 1.0f / (m.z + 1e-8f), bb);
        o.w = fmaf(acc.w * m.w, 1.0f / (m.w + 1e-8f), bb);
        y4[i] = o;
        p1 += (o.x + o.y) + (o.z + o.w);
        p2 = fmaf(o.x, o.x, fmaf(o.y, o.y, fmaf(o.z, o.z, fmaf(o.w, o.w, p2))));
    }
#pragma unroll
    for (int o = 16; o; o >>= 1) {
        p1 += __shfl_xor_sync(0xffffffffu, p1, o);
        p2 += __shfl_xor_sync(0xffffffffu, p2, o);
    }
    int warp = threadIdx.x >> 5, lane = threadIdx.x & 31;
    if (lane == 0) { r1[warp] = p1; r2[warp] = p2; }
    __syncthreads();
    if (threadIdx.x == 0) {
        float a = 0.f, b = 0.f;
        for (int w = 0; w < (int)(blockDim.x >> 5); w++) { a += r1[w]; b += r2[w]; }
        atomicAdd(&stats[0], (double)a);
        atomicAdd(&stats[16], (double)b);
    }
}

// Final BN (no relu), float4; affine of layer 6 computed per block.
__global__ void final_k(const float* __restrict__ y,
                        const double* __restrict__ st6,
                        const float* __restrict__ g6,
                        const float* __restrict__ bt6,
                        float* __restrict__ o) {
    __shared__ float2 t;
    if (threadIdx.x == 0) {
        double mean = st6[0] / (double)NPIX;
        double var  = st6[16] / (double)NPIX - mean * mean;
        float inv = rsqrtf((float)var + 1e-5f);
        float a = g6[0] * inv;
        t = make_float2(a, bt6[0] - (float)mean * a);
    }
    __syncthreads();
    float2 tt = t;
    const float4* y4 = (const float4*)y;
    float4* o4 = (float4*)o;
    for (long long i = (long long)blockIdx.x * blockDim.x + threadIdx.x;
         i < 1LL * HW; i += (long long)gridDim.x * blockDim.x) {
        float4 v = y4[i];
        v.x = fmaf(v.x, tt.x, tt.y);
        v.y = fmaf(v.y, tt.x, tt.y);
        v.z = fmaf(v.z, tt.x, tt.y);
        v.w = fmaf(v.w, tt.x, tt.y);
        o4[i] = v;
    }
}

// ---------------------------------------------------------------------------
static constexpr int tmma_smem(int K) {
    int TY = 8, TILE = 64;
    int NPX = TILE + K - 1, NPXW = (NPX + 7) & ~7, R = K + TY - 1;
    int MK = 1024 + 128;
    int AH = ((MK + R * NPXW * 4 + 127) / 128) * 128;
    return AH + 2 * R * NPXW * 32;
}
static constexpr int tmma1_smem() {
    int R = 18, MW = 80, ROWB = 64 * 32;
    int XM = 1024 + R * MW * 4;
    int AH = ((XM + R * MW * 4 + 127) / 128) * 128;
    return AH + 2 * R * ROWB;
}

extern "C" void kernel_launch(void* const* d_in, const int* in_sizes, int n_in,
                              void* d_out, int out_size) {
    (void)in_sizes; (void)n_in; (void)out_size;
    const float* x = (const float*)d_in[0];
    const float *wp[6], *bp[6], *gp[6], *btp[6];
    for (int i = 0; i < 6; i++) {
        wp[i]  = (const float*)d_in[1 + 4 * i];
        bp[i]  = (const float*)d_in[2 + 4 * i];
        gp[i]  = (const float*)d_in[3 + 4 * i];
        btp[i] = (const float*)d_in[4 + 4 * i];
    }

    float *h0, *h1, *m0, *m1;
    double* st;
    u32* bf;
    cudaGetSymbolAddress((void**)&h0, g_h0);
    cudaGetSymbolAddress((void**)&h1, g_h1);
    cudaGetSymbolAddress((void**)&m0, g_m0);
    cudaGetSymbolAddress((void**)&m1, g_m1);
    cudaGetSymbolAddress((void**)&st, g_stats);
    cudaGetSymbolAddress((void**)&bf, g_bfrag);

    cudaFuncSetAttribute(tmma_conv1_k, cudaFuncAttributeMaxDynamicSharedMemorySize, tmma1_smem());
    cudaFuncSetAttribute(tmma_conv_k<7, true>, cudaFuncAttributeMaxDynamicSharedMemorySize, tmma_smem(7));
    cudaFuncSetAttribute(tmma_conv_k<5, true>, cudaFuncAttributeMaxDynamicSharedMemorySize, tmma_smem(5));
    cudaFuncSetAttribute(tmma_conv_k<3, true>, cudaFuncAttributeMaxDynamicSharedMemorySize, tmma_smem(3));

    dim3 t1grid(1024 / 64, 1024 / 8, 4);
    dim3 tgrid(1024 / 64, 1024 / 8, 4);

    u32* bf2 = bf;
    u32* bf3 = bf + 49 * 256;
    u32* bf4p = bf + 74 * 256;
    u32* bf5 = bf + 83 * 256;
    u32* bf1 = bf + 92 * 256;

    prep_all_b<<<26, 256>>>(wp[0], wp[1], wp[2], wp[3], wp[4], bf, st);

    tmma_conv1_k<<<t1grid, 128, tmma1_smem()>>>(
        x, 2LL * HW, x + HW, 2LL * HW, bf1, bp[0], h0, m0, st + 0);

    tmma_conv_k<7, true><<<tgrid, 128, tmma_smem(7)>>>(
        h0, 16LL * HW, m0, (long long)HW, bf2, bp[1],
        st + 0, gp[0], btp[0], h1, m1, st + 32);

    tmma_conv_k<5, true><<<tgrid, 128, tmma_smem(5)>>>(
        h1, 16LL * HW, m1, (long long)HW, bf3, bp[2],
        st + 32, gp[1], btp[1], h0, m0, st + 64);

    tmma_conv_k<3, true><<<tgrid, 128, tmma_smem(3)>>>(
        h0, 16LL * HW, m0, (long long)HW, bf4p, bp[3],
        st + 64, gp[2], btp[2], h1, m1, st + 96);

    tmma_conv_k<3, true><<<tgrid, 128, tmma_smem(3)>>>(
        h1, 16LL * HW, m1, (long long)HW, bf5, bp[4],
        st + 96, gp[3], btp[3], h0, m0, st + 128);

    conv1x1_k<<<1184, 256>>>(h0, m0, wp[5], bp[5],
                             st + 128, gp[4], btp[4], h1, st + 160);

    final_k<<<2048, 256>>>(h1, st + 160, gp[5], btp[5], (float*)d_out);
}

// round 17
// speedup vs baseline: 1.0234x; 1.0234x over previous
#include <cuda_runtime.h>
#include <cuda_bf16.h>
#include <math.h>

// ---------------------------------------------------------------------------
// SparseConvNet: 6 partial-conv layers. N=4, H=W=1024.
// Round 17: exact revert to R14 (measured best, 1801us). TY=8 row-sweep MMA,
// single-pass B register cache, fused mask+A staging, scalar L1 staging.
// ---------------------------------------------------------------------------

#define HW   (1024 * 1024)
#define IMW  1024
#define NPIX (4LL * HW)

__device__ float  g_h0[4 * 16 * HW];
__device__ float  g_h1[4 * 16 * HW];
__device__ float  g_m0[4 * HW];
__device__ float  g_m1[4 * HW];
__device__ double g_stats[6 * 32];
__device__ unsigned int g_bfrag[103 * 2 * 32 * 4];  // 49+25+9+9 + 11 (L1) taps

typedef unsigned long long u64;
typedef unsigned int u32;
typedef unsigned short u16;

__device__ __forceinline__ u32 smem_u32(const void* p) {
    u32 a;
    asm("{ .reg .u64 t; cvta.to.shared.u64 t, %1; cvt.u32.u64 %0, t; }"
        : "=r"(a) : "l"(p));
    return a;
}
__device__ __forceinline__ void ldsm4(u32* r, u32 a) {
    asm volatile("ldmatrix.sync.aligned.m8n8.x4.shared.b16 {%0,%1,%2,%3}, [%4];"
                 : "=r"(r[0]), "=r"(r[1]), "=r"(r[2]), "=r"(r[3]) : "r"(a));
}
__device__ __forceinline__ void mma16816(float* d, const u32* a, u32 b0, u32 b1) {
    asm volatile(
        "mma.sync.aligned.m16n8k16.row.col.f32.bf16.bf16.f32 "
        "{%0,%1,%2,%3}, {%4,%5,%6,%7}, {%8,%9}, {%0,%1,%2,%3};"
        : "+f"(d[0]), "+f"(d[1]), "+f"(d[2]), "+f"(d[3])
        : "r"(a[0]), "r"(a[1]), "r"(a[2]), "r"(a[3]), "r"(b0), "r"(b1));
}
// truncation hi/lo split (scalar, used in prep): hi = top16, lo = RN(t - hi)
__device__ __forceinline__ void bsplit(float t, u16& h, u16& l) {
    u32 u = __float_as_uint(t);
    h = (u16)(u >> 16);
    float fh = __uint_as_float(u & 0xFFFF0000u);
    l = __bfloat16_as_ushort(__float2bfloat16(t - fh));
}
// packed pair split: h = hi16(v0)|hi16(v1)<<16 via PRMT; l = bf16x2 of residuals
__device__ __forceinline__ void bsplit2(float v0, float v1, u32& h, u32& l) {
    u32 u0 = __float_as_uint(v0), u1 = __float_as_uint(v1);
    asm("prmt.b32 %0, %1, %2, 0x7632;" : "=r"(h) : "r"(u0), "r"(u1));
    float f0 = __uint_as_float(u0 & 0xFFFF0000u);
    float f1 = __uint_as_float(u1 & 0xFFFF0000u);
    asm("cvt.rn.bf16x2.f32 %0, %1, %2;" : "=r"(l) : "f"(v1 - f1), "f"(v0 - f0));
}

// ---------------------------------------------------------------------------
// Combined prep: zero stats + B fragments.
// Taps 0..48: L2(K=7); 49..73: L3(K=5); 74..82: L4(K=3); 83..91: L5(K=3);
// 92..102: L1 (11 dy-taps, "ci" = dx of the 11-wide row, zero-padded to 16).
// ---------------------------------------------------------------------------
__global__ void prep_all_b(const float* __restrict__ w1, const float* __restrict__ w2,
                           const float* __restrict__ w3, const float* __restrict__ w4,
                           const float* __restrict__ w5,
                           u32* __restrict__ bf, double* __restrict__ st) {
    if (blockIdx.x == 0 && threadIdx.x < 192) st[threadIdx.x] = 0.0;
    const int total = 103 * 2 * 32;
    for (int i = blockIdx.x * blockDim.x + threadIdx.x; i < total;
         i += gridDim.x * blockDim.x) {
        int lane = i & 31;
        int half = (i >> 5) & 1;
        int gt = i >> 6;
        int k0 = (lane & 3) * 2, nn = lane >> 2;
        u32 out[4];
        if (gt >= 92) {
            int dy = gt - 92;
#pragma unroll
            for (int t = 0; t < 2; t++) {
#pragma unroll
                for (int kk = 0; kk < 2; kk++) {
                    int co = t * 8 + nn;
                    int dx = k0 + kk * 8;
                    float v0 = (dx < 11) ? w1[co * 121 + dy * 11 + dx] : 0.f;
                    float v1 = (dx + 1 < 11) ? w1[co * 121 + dy * 11 + dx + 1] : 0.f;
                    u16 h0, l0, h1, l1;
                    bsplit(v0, h0, l0);
                    bsplit(v1, h1, l1);
                    u16 a = half ? l0 : h0, b = half ? l1 : h1;
                    out[t * 2 + kk] = (u32)a | ((u32)b << 16);
                }
            }
        } else {
            const float* w;
            int K, tap;
            if (gt < 49)      { w = w2; K = 7; tap = gt; }
            else if (gt < 74) { w = w3; K = 5; tap = gt - 49; }
            else if (gt < 83) { w = w4; K = 3; tap = gt - 74; }
            else              { w = w5; K = 3; tap = gt - 83; }
            int dy = tap / K, dx = tap - dy * K;
#pragma unroll
            for (int t = 0; t < 2; t++) {
#pragma unroll
                for (int kk = 0; kk < 2; kk++) {
                    int co = t * 8 + nn;
                    int k = k0 + kk * 8;
                    float v0 = w[((co * 16 + k) * K + dy) * K + dx];
                    float v1 = w[((co * 16 + k + 1) * K + dy) * K + dx];
                    u16 h0, l0, h1, l1;
                    bsplit(v0, h0, l0);
                    bsplit(v1, h1, l1);
                    u16 a = half ? l0 : h0, b = half ? l1 : h1;
                    out[t * 2 + kk] = (u32)a | ((u32)b << 16);
                }
            }
        }
        ((uint4*)bf)[i] = make_uint4(out[0], out[1], out[2], out[3]);
    }
}

// ---------------------------------------------------------------------------
// Tensor-core partial-conv layer (cin=cout=16), layers 2-5. TY=8, fused
// mask+A staging, single-pass B register cache.
// ---------------------------------------------------------------------------
template <int K, bool AFF>
__global__ void __launch_bounds__(128, (K <= 3) ? 4 : 3) tmma_conv_k(
    const float* __restrict__ in, long long inNS,
    const float* __restrict__ mk, long long mkNS,
    const u32* __restrict__ bfrag, const float* __restrict__ bias,
    const double* __restrict__ stPrev,
    const float* __restrict__ gamPrev, const float* __restrict__ betPrev,
    float* __restrict__ outH, float* __restrict__ outM,
    double* __restrict__ stats) {
    constexpr int TY = 8, P = K / 2, TILE = 64;
    constexpr int NPX = TILE + K - 1;
    constexpr int NPXW = (NPX + 7) & ~7;
    constexpr int R = K + TY - 1;
    constexpr int ROWB = NPXW * 32;
    constexpr int SR_OFF = 0;
    constexpr int AB_OFF = 1024;
    constexpr int MK_OFF = AB_OFF + 128;
    constexpr int AH_OFF = ((MK_OFF + R * NPXW * 4 + 127) / 128) * 128;
    constexpr int AL_OFF = AH_OFF + R * ROWB;

    extern __shared__ char smx[];
    float*  sR  = (float*)(smx + SR_OFF);
    float2* sAB = (float2*)(smx + AB_OFF);
    float*  sMk = (float*)(smx + MK_OFF);
    const u32 sb = smem_u32(smx);

    const int tid = threadIdx.x;
    const int wid = tid >> 5;
    const int lane = tid & 31;
    const int n  = blockIdx.z;
    const int x0 = blockIdx.x * TILE;
    const int y0 = blockIdx.y * TY;

    if (tid < 16) {
        if (AFF) {
            double mean = stPrev[tid] / (double)NPIX;
            double var  = stPrev[16 + tid] / (double)NPIX - mean * mean;
            float inv = rsqrtf((float)var + 1e-5f);
            float a = gamPrev[tid] * inv;
            sAB[tid] = make_float2(a, betPrev[tid] - (float)mean * a);
        } else {
            sAB[tid] = make_float2(1.f, 0.f);
        }
    }
    __syncthreads();

    float2 abr[16];
#pragma unroll
    for (int ci = 0; ci < 16; ci++) abr[ci] = sAB[ci];

    // ---- fused mask + A staging (single loop) ----
    const float* mkn = mk + (long long)n * mkNS;
    const float* inn = in + (long long)n * inNS;
    for (int i = tid; i < R * NPX; i += 128) {
        int r = i / NPX, p = i - r * NPX;
        int gy = y0 - P + r, gx = x0 - P + p;
        bool ok = (unsigned)gy < 1024u && (unsigned)gx < 1024u;
        long long goff = (long long)gy * IMW + gx;
        float m = ok ? mkn[goff] : 0.f;
        sMk[r * NPXW + p] = m;
        const float* ip = inn + goff;
        u32 hp[8], lp[8];
#pragma unroll
        for (int c2 = 0; c2 < 8; c2++) {
            float v0 = ok ? ip[(long long)(2 * c2) * HW] : 0.f;
            float v1 = ok ? ip[(long long)(2 * c2 + 1) * HW] : 0.f;
            if (AFF) {
                v0 = fmaxf(fmaf(v0, abr[2 * c2].x, abr[2 * c2].y), 0.f);
                v1 = fmaxf(fmaf(v1, abr[2 * c2 + 1].x, abr[2 * c2 + 1].y), 0.f);
            }
            v0 *= m;
            v1 *= m;
            bsplit2(v0, v1, hp[c2], lp[c2]);
        }
        u32 s = ((p >> 2) & 1) * 16;
        char* ah = smx + AH_OFF + r * ROWB + p * 32;
        char* al = smx + AL_OFF + r * ROWB + p * 32;
        *(uint4*)(ah + s)        = make_uint4(hp[0], hp[1], hp[2], hp[3]);
        *(uint4*)(ah + (16 ^ s)) = make_uint4(hp[4], hp[5], hp[6], hp[7]);
        *(uint4*)(al + s)        = make_uint4(lp[0], lp[1], lp[2], lp[3]);
        *(uint4*)(al + (16 ^ s)) = make_uint4(lp[4], lp[5], lp[6], lp[7]);
    }
    __syncthreads();

    const int seg = wid;
    float D[TY][2][4];
#pragma unroll
    for (int y = 0; y < TY; y++)
#pragma unroll
        for (int t = 0; t < 2; t++)
#pragma unroll
            for (int j = 0; j < 4; j++) D[y][t][j] = 0.f;

    const int l15 = lane & 15;
    const int kh = lane >> 4;
    const uint4* bf4 = (const uint4*)bfrag;

#pragma unroll 1
    for (int dx = 0; dx < K; dx++) {
        u32 sw = (u32)(((l15 + dx) >> 2) & 1);
        u32 apx = (u32)(seg * 16 + l15 + dx);
        u32 aoff = apx * 32 + (((u32)kh ^ sw) * 16);
        u32 aH = sb + AH_OFF + aoff;
        u32 aL = sb + AL_OFF + aoff;
        uint4 BH[K], BL[K];
#pragma unroll
        for (int dy = 0; dy < K; dy++) {
            BH[dy] = bf4[((dy * K + dx) * 2 + 0) * 32 + lane];
            BL[dy] = bf4[((dy * K + dx) * 2 + 1) * 32 + lane];
        }
#pragma unroll
        for (int r = 0; r < R; r++) {
            u32 Ah[4], Al[4];
            ldsm4(Ah, aH + r * ROWB);
            ldsm4(Al, aL + r * ROWB);
#pragma unroll
            for (int dy = 0; dy < K; dy++) {
                const int y = r - dy;
                if (y >= 0 && y < TY) {
                    mma16816(D[y][0], Ah, BH[dy].x, BH[dy].y);
                    mma16816(D[y][1], Ah, BH[dy].z, BH[dy].w);
                    mma16816(D[y][0], Al, BH[dy].x, BH[dy].y);
                    mma16816(D[y][1], Al, BH[dy].z, BH[dy].w);
                    mma16816(D[y][0], Ah, BL[dy].x, BL[dy].y);
                    mma16816(D[y][1], Ah, BL[dy].z, BL[dy].w);
                }
            }
        }
    }

    const int pxl = lane & 15, half = lane >> 4;
    float hsum[R], hmax[R];
    {
        const float* mb = sMk + seg * 16 + pxl;
#pragma unroll
        for (int r = 0; r < R; r++) {
            float s = 0.f, mx = 0.f;
#pragma unroll
            for (int dxm = 0; dxm < K; dxm++) {
                float m = mb[r * NPXW + dxm];
                s += m;
                mx = fmaxf(mx, m);
            }
            hsum[r] = s;
            hmax[r] = mx;
        }
    }
    float invv[4];
#pragma unroll
    for (int j = 0; j < 4; j++) {
        int y = half + 2 * j;
        float s = 0.f, mx = 0.f;
#pragma unroll
        for (int dy = 0; dy < K; dy++) {
            s += hsum[y + dy];
            mx = fmaxf(mx, hmax[y + dy]);
        }
        invv[j] = 1.0f / (s + 1e-8f);
        outM[(long long)n * HW + (long long)(y0 + y) * IMW + x0 + seg * 16 + pxl] = mx;
    }

    float bco[4];
#pragma unroll
    for (int t = 0; t < 2; t++)
#pragma unroll
        for (int j = 0; j < 2; j++)
            bco[t * 2 + j] = bias[t * 8 + (lane & 3) * 2 + j];
    float p1[4] = {0.f, 0.f, 0.f, 0.f}, p2[4] = {0.f, 0.f, 0.f, 0.f};
    const int pxa = seg * 16 + (lane >> 2);

#pragma unroll
    for (int y = 0; y < TY; y++) {
        float vsel = invv[y >> 1];
        float inva = __shfl_sync(0xffffffffu, vsel, ((y & 1) << 4) + (lane >> 2));
        float invb = __shfl_sync(0xffffffffu, vsel, ((y & 1) << 4) + (lane >> 2) + 8);
        int gy = y0 + y;
        float* hb = outH + (long long)n * 16 * HW + (long long)gy * IMW + x0;
#pragma unroll
        for (int t = 0; t < 2; t++) {
#pragma unroll
            for (int j = 0; j < 2; j++) {
                int co = t * 8 + (lane & 3) * 2 + j;
                float bc = bco[t * 2 + j];
                float v0 = fmaf(D[y][t][j], inva, bc);
                float v1 = fmaf(D[y][t][j + 2], invb, bc);
                hb[(long long)co * HW + pxa] = v0;
                hb[(long long)co * HW + pxa + 8] = v1;
                p1[t * 2 + j] += v0 + v1;
                p2[t * 2 + j] = fmaf(v0, v0, fmaf(v1, v1, p2[t * 2 + j]));
            }
        }
    }
#pragma unroll
    for (int k = 0; k < 4; k++) {
#pragma unroll
        for (int o = 4; o < 32; o <<= 1) {
            p1[k] += __shfl_xor_sync(0xffffffffu, p1[k], o);
            p2[k] += __shfl_xor_sync(0xffffffffu, p2[k], o);
        }
    }
    if (lane < 4) {
#pragma unroll
        for (int t = 0; t < 2; t++)
#pragma unroll
            for (int j = 0; j < 2; j++) {
                int co = t * 8 + lane * 2 + j;
                sR[(co * 2 + 0) * 4 + wid] = p1[t * 2 + j];
                sR[(co * 2 + 1) * 4 + wid] = p2[t * 2 + j];
            }
    }
    __syncthreads();
    if (tid < 32) {
        int co = tid >> 1, which = tid & 1;
        float v = sR[tid * 4 + 0] + sR[tid * 4 + 1] + sR[tid * 4 + 2] + sR[tid * 4 + 3];
        atomicAdd(&stats[which * 16 + co], (double)v);
    }
}

// ---------------------------------------------------------------------------
// Layer 1 tensor-core partial conv (cin=1, K=11), TY=8: dx taps packed as MMA
// channels (scalar sliding-window staging — measured faster than float4).
// ---------------------------------------------------------------------------
__global__ void __launch_bounds__(128, 2) tmma_conv1_k(
    const float* __restrict__ in, long long inNS,
    const float* __restrict__ mk, long long mkNS,
    const u32* __restrict__ bfrag, const float* __restrict__ bias,
    float* __restrict__ outH, float* __restrict__ outM,
    double* __restrict__ stats) {
    constexpr int K = 11, TY = 8, P = 5, TILE = 64;
    constexpr int R = K + TY - 1;          // 18 window rows
    constexpr int MW = 80;                 // mask/xm row width (64+15 pad)
    constexpr int MUSE = TILE + K - 1;     // 74 meaningful columns
    constexpr int ROWB = TILE * 32;        // A row bytes (64 px * 32B)
    constexpr int SR_OFF = 0;
    constexpr int MK_OFF = 1024;
    constexpr int XM_OFF = MK_OFF + R * MW * 4;
    constexpr int AH_OFF = ((XM_OFF + R * MW * 4 + 127) / 128) * 128;
    constexpr int AL_OFF = AH_OFF + R * ROWB;

    extern __shared__ char smx[];
    float* sR  = (float*)(smx + SR_OFF);
    float* sMk = (float*)(smx + MK_OFF);
    float* sXm = (float*)(smx + XM_OFF);
    const u32 sb = smem_u32(smx);

    const int tid = threadIdx.x;
    const int wid = tid >> 5;
    const int lane = tid & 31;
    const int n  = blockIdx.z;
    const int x0 = blockIdx.x * TILE;
    const int y0 = blockIdx.y * TY;

    // ---- stage mask + xm rows ----
    const float* mkn = mk + (long long)n * mkNS;
    const float* inn = in + (long long)n * inNS;
    for (int i = tid; i < R * MW; i += 128) {
        int r = i / MW, j = i - r * MW;
        int gy = y0 - P + r, gx = x0 - P + j;
        float m = 0.f, v = 0.f;
        if ((unsigned)gy < 1024u && (unsigned)gx < 1024u && j < MUSE) {
            m = mkn[gy * IMW + gx];
            v = inn[gy * IMW + gx];
        }
        sMk[i] = m;
        sXm[i] = v * m;
    }
    __syncthreads();

    // ---- stage A: A[r][px][c] = xm[r][px + c]  (c = dx tap, 0..15) ----
    for (int i = tid; i < R * TILE; i += 128) {
        int r = i >> 6, p = i & 63;
        const float* xr = sXm + r * MW + p;
        u32 hp[8], lp[8];
#pragma unroll
        for (int c2 = 0; c2 < 8; c2++)
            bsplit2(xr[2 * c2], xr[2 * c2 + 1], hp[c2], lp[c2]);
        u32 s = ((p >> 2) & 1) * 16;
        char* ah = smx + AH_OFF + r * ROWB + p * 32;
        char* al = smx + AL_OFF + r * ROWB + p * 32;
        *(uint4*)(ah + s)        = make_uint4(hp[0], hp[1], hp[2], hp[3]);
        *(uint4*)(ah + (16 ^ s)) = make_uint4(hp[4], hp[5], hp[6], hp[7]);
        *(uint4*)(al + s)        = make_uint4(lp[0], lp[1], lp[2], lp[3]);
        *(uint4*)(al + (16 ^ s)) = make_uint4(lp[4], lp[5], lp[6], lp[7]);
    }
    __syncthreads();

    // ---- MMA mainloop: r-sweep, B per dy from global (L1-resident) ----
    const int seg = wid;
    float D[TY][2][4];
#pragma unroll
    for (int y = 0; y < TY; y++)
#pragma unroll
        for (int t = 0; t < 2; t++)
#pragma unroll
            for (int j = 0; j < 4; j++) D[y][t][j] = 0.f;

    const int l15 = lane & 15;
    const int kh = lane >> 4;
    const uint4* bf4 = (const uint4*)bfrag;
    {
        u32 sw = (u32)((l15 >> 2) & 1);
        u32 aoff = (u32)(seg * 16 + l15) * 32 + (((u32)kh ^ sw) * 16);
        u32 aH = sb + AH_OFF + aoff;
        u32 aL = sb + AL_OFF + aoff;
#pragma unroll
        for (int r = 0; r < R; r++) {
            u32 Ah[4], Al[4];
            ldsm4(Ah, aH + r * ROWB);
            ldsm4(Al, aL + r * ROWB);
#pragma unroll
            for (int dy = 0; dy < K; dy++) {
                const int y = r - dy;
                if (y >= 0 && y < TY) {
                    uint4 BH = bf4[(dy * 2 + 0) * 32 + lane];
                    uint4 BL = bf4[(dy * 2 + 1) * 32 + lane];
                    mma16816(D[y][0], Ah, BH.x, BH.y);
                    mma16816(D[y][1], Ah, BH.z, BH.w);
                    mma16816(D[y][0], Al, BH.x, BH.y);
                    mma16816(D[y][1], Al, BH.z, BH.w);
                    mma16816(D[y][0], Ah, BL.x, BL.y);
                    mma16816(D[y][1], Ah, BL.z, BL.w);
                }
            }
        }
    }

    // ---- separable mask-sum conv + maxpool (lane owns rows half+2j) ----
    const int pxl = lane & 15, half = lane >> 4;
    float hsum[R], hmax[R];
    {
        const float* mb = sMk + seg * 16 + pxl;
#pragma unroll
        for (int r = 0; r < R; r++) {
            float s = 0.f, mx = 0.f;
#pragma unroll
            for (int dxm = 0; dxm < K; dxm++) {
                float m = mb[r * MW + dxm];
                s += m;
                mx = fmaxf(mx, m);
            }
            hsum[r] = s;
            hmax[r] = mx;
        }
    }
    float invv[4];
#pragma unroll
    for (int j = 0; j < 4; j++) {
        int y = half + 2 * j;
        float s = 0.f, mx = 0.f;
#pragma unroll
        for (int dy = 0; dy < K; dy++) {
            s += hsum[y + dy];
            mx = fmaxf(mx, hmax[y + dy]);
        }
        invv[j] = 1.0f / (s + 1e-8f);
        outM[(long long)n * HW + (long long)(y0 + y) * IMW + x0 + seg * 16 + pxl] = mx;
    }

    // ---- epilogue ----
    float bco[4];
#pragma unroll
    for (int t = 0; t < 2; t++)
#pragma unroll
        for (int j = 0; j < 2; j++)
            bco[t * 2 + j] = bias[t * 8 + (lane & 3) * 2 + j];
    float p1[4] = {0.f, 0.f, 0.f, 0.f}, p2[4] = {0.f, 0.f, 0.f, 0.f};
    const int pxa = seg * 16 + (lane >> 2);

#pragma unroll
    for (int y = 0; y < TY; y++) {
        float vsel = invv[y >> 1];
        float inva = __shfl_sync(0xffffffffu, vsel, ((y & 1) << 4) + (lane >> 2));
        float invb = __shfl_sync(0xffffffffu, vsel, ((y & 1) << 4) + (lane >> 2) + 8);
        int gy = y0 + y;
        float* hb = outH + (long long)n * 16 * HW + (long long)gy * IMW + x0;
#pragma unroll
        for (int t = 0; t < 2; t++) {
#pragma unroll
            for (int j = 0; j < 2; j++) {
                int co = t * 8 + (lane & 3) * 2 + j;
                float bc = bco[t * 2 + j];
                float v0 = fmaf(D[y][t][j], inva, bc);
                float v1 = fmaf(D[y][t][j + 2], invb, bc);
                hb[(long long)co * HW + pxa] = v0;
                hb[(long long)co * HW + pxa + 8] = v1;
                p1[t * 2 + j] += v0 + v1;
                p2[t * 2 + j] = fmaf(v0, v0, fmaf(v1, v1, p2[t * 2 + j]));
            }
        }
    }
#pragma unroll
    for (int k = 0; k < 4; k++) {
#pragma unroll
        for (int o = 4; o < 32; o <<= 1) {
            p1[k] += __shfl_xor_sync(0xffffffffu, p1[k], o);
            p2[k] += __shfl_xor_sync(0xffffffffu, p2[k], o);
        }
    }
    if (lane < 4) {
#pragma unroll
        for (int t = 0; t < 2; t++)
#pragma unroll
            for (int j = 0; j < 2; j++) {
                int co = t * 8 + lane * 2 + j;
                sR[(co * 2 + 0) * 4 + wid] = p1[t * 2 + j];
                sR[(co * 2 + 1) * 4 + wid] = p2[t * 2 + j];
            }
    }
    __syncthreads();
    if (tid < 32) {
        int co = tid >> 1, which = tid & 1;
        float v = sR[tid * 4 + 0] + sR[tid * 4 + 1] + sR[tid * 4 + 2] + sR[tid * 4 + 3];
        atomicAdd(&stats[which * 16 + co], (double)v);
    }
}

// ---------------------------------------------------------------------------
// Layer 6: 1x1 partial conv, 16 -> 1; float4 (4 px/thread); affine in-block.
// ---------------------------------------------------------------------------
__global__ void conv1x1_k(const float* __restrict__ h,
                          const float* __restrict__ mk,
                          const float* __restrict__ w6,
                          const float* __restrict__ b6,
                          const double* __restrict__ st5,
                          const float* __restrict__ g5,
                          const float* __restrict__ bt5,
                          float* __restrict__ y,
                          double* __restrict__ stats) {
    __shared__ float swv[16];
    __shared__ float2 sab[16];
    __shared__ float r1[8], r2[8];
    if (threadIdx.x < 16) {
        swv[threadIdx.x] = w6[threadIdx.x];
        double mean = st5[threadIdx.x] / (double)NPIX;
        double var  = st5[16 + threadIdx.x] / (double)NPIX - mean * mean;
        float inv = rsqrtf((float)var + 1e-5f);
        float a = g5[threadIdx.x] * inv;
        sab[threadIdx.x] = make_float2(a, bt5[threadIdx.x] - (float)mean * a);
    }
    __syncthreads();
    float bb = b6[0];
    float p1 = 0.f, p2 = 0.f;
    const float4* mk4 = (const float4*)mk;
    float4* y4 = (float4*)y;
    for (long long i = (long long)blockIdx.x * blockDim.x + threadIdx.x;
         i < 1LL * HW; i += (long long)gridDim.x * blockDim.x) {
        long long n = i >> 18;
        long long p4 = i & ((HW >> 2) - 1);
        float4 m = mk4[i];
        float4 acc = make_float4(0.f, 0.f, 0.f, 0.f);
        const float4* hb = (const float4*)(h + (n * 16) * HW) + p4;
#pragma unroll
        for (int c = 0; c < 16; c++) {
            float4 v = hb[(long long)c * (HW >> 2)];
            float2 ab = sab[c];
            float wv = swv[c];
            acc.x = fmaf(wv, fmaxf(fmaf(v.x, ab.x, ab.y), 0.f), acc.x);
            acc.y = fmaf(wv, fmaxf(fmaf(v.y, ab.x, ab.y), 0.f), acc.y);
            acc.z = fmaf(wv, fmaxf(fmaf(v.z, ab.x, ab.y), 0.f), acc.z);
            acc.w = fmaf(wv, fmaxf(fmaf(v.w, ab.x, ab.y), 0.f), acc.w);
        }
        float4 o;
        o.x = fmaf(acc.x * m.x, 1.0f / (m.x + 1e-8f), bb);
        o.y = fmaf(acc.y * m.y, 1.0f / (m.y + 1e-8f), bb);
        o.z = fmaf(acc.z * m.z, 1.0f / (m.z + 1e-8f), bb);
        o.w = fmaf(acc.w * m.w, 1.0f / (m.w + 1e-8f), bb);
        y4[i] = o;
        p1 += (o.x + o.y) + (o.z + o.w);
        p2 = fmaf(o.x, o.x, fmaf(o.y, o.y, fmaf(o.z, o.z, fmaf(o.w, o.w, p2))));
    }
#pragma unroll
    for (int o = 16; o; o >>= 1) {
        p1 += __shfl_xor_sync(0xffffffffu, p1, o);
        p2 += __shfl_xor_sync(0xffffffffu, p2, o);
    }
    int warp = threadIdx.x >> 5, lane = threadIdx.x & 31;
    if (lane == 0) { r1[warp] = p1; r2[warp] = p2; }
    __syncthreads();
    if (threadIdx.x == 0) {
        float a = 0.f, b = 0.f;
        for (int w = 0; w < (int)(blockDim.x >> 5); w++) { a += r1[w]; b += r2[w]; }
        atomicAdd(&stats[0], (double)a);
        atomicAdd(&stats[16], (double)b);
    }
}

// Final BN (no relu), float4; affine of layer 6 computed per block.
__global__ void final_k(const float* __restrict__ y,
                        const double* __restrict__ st6,
                        const float* __restrict__ g6,
                        const float* __restrict__ bt6,
                        float* __restrict__ o) {
    __shared__ float2 t;
    if (threadIdx.x == 0) {
        double mean = st6[0] / (double)NPIX;
        double var  = st6[16] / (double)NPIX - mean * mean;
        float inv = rsqrtf((float)var + 1e-5f);
        float a = g6[0] * inv;
        t = make_float2(a, bt6[0] - (float)mean * a);
    }
    __syncthreads();
    float2 tt = t;
    const float4* y4 = (const float4*)y;
    float4* o4 = (float4*)o;
    for (long long i = (long long)blockIdx.x * blockDim.x + threadIdx.x;
         i < 1LL * HW; i += (long long)gridDim.x * blockDim.x) {
        float4 v = y4[i];
        v.x = fmaf(v.x, tt.x, tt.y);
        v.y = fmaf(v.y, tt.x, tt.y);
        v.z = fmaf(v.z, tt.x, tt.y);
        v.w = fmaf(v.w, tt.x, tt.y);
        o4[i] = v;
    }
}

// ---------------------------------------------------------------------------
static constexpr int tmma_smem(int K) {
    int TY = 8, TILE = 64;
    int NPX = TILE + K - 1, NPXW = (NPX + 7) & ~7, R = K + TY - 1;
    int MK = 1024 + 128;
    int AH = ((MK + R * NPXW * 4 + 127) / 128) * 128;
    return AH + 2 * R * NPXW * 32;
}
static constexpr int tmma1_smem() {
    int R = 18, MW = 80, ROWB = 64 * 32;
    int XM = 1024 + R * MW * 4;
    int AH = ((XM + R * MW * 4 + 127) / 128) * 128;
    return AH + 2 * R * ROWB;
}

extern "C" void kernel_launch(void* const* d_in, const int* in_sizes, int n_in,
                              void* d_out, int out_size) {
    (void)in_sizes; (void)n_in; (void)out_size;
    const float* x = (const float*)d_in[0];
    const float *wp[6], *bp[6], *gp[6], *btp[6];
    for (int i = 0; i < 6; i++) {
        wp[i]  = (const float*)d_in[1 + 4 * i];
        bp[i]  = (const float*)d_in[2 + 4 * i];
        gp[i]  = (const float*)d_in[3 + 4 * i];
        btp[i] = (const float*)d_in[4 + 4 * i];
    }

    float *h0, *h1, *m0, *m1;
    double* st;
    u32* bf;
    cudaGetSymbolAddress((void**)&h0, g_h0);
    cudaGetSymbolAddress((void**)&h1, g_h1);
    cudaGetSymbolAddress((void**)&m0, g_m0);
    cudaGetSymbolAddress((void**)&m1, g_m1);
    cudaGetSymbolAddress((void**)&st, g_stats);
    cudaGetSymbolAddress((void**)&bf, g_bfrag);

    cudaFuncSetAttribute(tmma_conv1_k, cudaFuncAttributeMaxDynamicSharedMemorySize, tmma1_smem());
    cudaFuncSetAttribute(tmma_conv_k<7, true>, cudaFuncAttributeMaxDynamicSharedMemorySize, tmma_smem(7));
    cudaFuncSetAttribute(tmma_conv_k<5, true>, cudaFuncAttributeMaxDynamicSharedMemorySize, tmma_smem(5));
    cudaFuncSetAttribute(tmma_conv_k<3, true>, cudaFuncAttributeMaxDynamicSharedMemorySize, tmma_smem(3));

    dim3 t1grid(1024 / 64, 1024 / 8, 4);
    dim3 tgrid(1024 / 64, 1024 / 8, 4);

    u32* bf2 = bf;
    u32* bf3 = bf + 49 * 256;
    u32* bf4p = bf + 74 * 256;
    u32* bf5 = bf + 83 * 256;
    u32* bf1 = bf + 92 * 256;

    prep_all_b<<<26, 256>>>(wp[0], wp[1], wp[2], wp[3], wp[4], bf, st);

    tmma_conv1_k<<<t1grid, 128, tmma1_smem()>>>(
        x, 2LL * HW, x + HW, 2LL * HW, bf1, bp[0], h0, m0, st + 0);

    tmma_conv_k<7, true><<<tgrid, 128, tmma_smem(7)>>>(
        h0, 16LL * HW, m0, (long long)HW, bf2, bp[1],
        st + 0, gp[0], btp[0], h1, m1, st + 32);

    tmma_conv_k<5, true><<<tgrid, 128, tmma_smem(5)>>>(
        h1, 16LL * HW, m1, (long long)HW, bf3, bp[2],
        st + 32, gp[1], btp[1], h0, m0, st + 64);

    tmma_conv_k<3, true><<<tgrid, 128, tmma_smem(3)>>>(
        h0, 16LL * HW, m0, (long long)HW, bf4p, bp[3],
        st + 64, gp[2], btp[2], h1, m1, st + 96);

    tmma_conv_k<3, true><<<tgrid, 128, tmma_smem(3)>>>(
        h1, 16LL * HW, m1, (long long)HW, bf5, bp[4],
        st + 96, gp[3], btp[3], h0, m0, st + 128);

    conv1x1_k<<<1184, 256>>>(h0, m0, wp[5], bp[5],
                             st + 128, gp[4], btp[4], h1, st + 160);

    final_k<<<2048, 256>>>(h1, st + 160, gp[5], btp[5], (float*)d_out);
}